// round 4
// baseline (speedup 1.0000x reference)
#include <cuda_runtime.h>
#include <cstdint>

#define IN_DIM  8192
#define OUT_DIM 8192
#define TPB     256
#define VPT     (IN_DIM / 4 / TPB)   // float4 loads per thread per row = 8
#define THRESH  50.0f
// rows of `states` kept L2-resident via evict_last: 3072 rows * 32KB = 96 MB (< 126 MB L2)
#define PIN_ROWS 3072

__device__ __forceinline__ uint64_t policy_evict_last() {
    uint64_t p;
    asm("createpolicy.fractional.L2::evict_last.b64 %0, 1.0;" : "=l"(p));
    return p;
}
__device__ __forceinline__ uint64_t policy_evict_first() {
    uint64_t p;
    asm("createpolicy.fractional.L2::evict_first.b64 %0, 1.0;" : "=l"(p));
    return p;
}
__device__ __forceinline__ float4 ldg_hint(const float4* p, uint64_t pol) {
    float4 v;
    asm volatile("ld.global.L2::cache_hint.v4.f32 {%0,%1,%2,%3}, [%4], %5;"
                 : "=f"(v.x), "=f"(v.y), "=f"(v.z), "=f"(v.w)
                 : "l"(p), "l"(pol));
    return v;
}
__device__ __forceinline__ void stg_hint(float4* p, float4 v, uint64_t pol) {
    asm volatile("st.global.L2::cache_hint.v4.f32 [%0], {%1,%2,%3,%4}, %5;"
                 :: "l"(p), "f"(v.x), "f"(v.y), "f"(v.z), "f"(v.w), "l"(pol)
                 : "memory");
}

__global__ __launch_bounds__(TPB)
void snn_fused_kernel(const float* __restrict__ spike_input,
                      const float* __restrict__ states,
                      const float* __restrict__ v_mem,
                      const float* __restrict__ v_th,
                      const float* __restrict__ elig,
                      const float* __restrict__ noise,
                      float* __restrict__ out)
{
    __shared__ float s_warp[TPB / 32];
    __shared__ float s_spk;

    const int row = blockIdx.x;
    const int tid = threadIdx.x;

    const uint64_t pol_last  = policy_evict_last();
    const uint64_t pol_first = policy_evict_first();
    const uint64_t pol_states = (row < PIN_ROWS) ? pol_last : pol_first;

    const float4* sp4  = reinterpret_cast<const float4*>(spike_input);
    const float4* st4  = reinterpret_cast<const float4*>(states + (size_t)row * IN_DIM);
    const float4* el4  = reinterpret_cast<const float4*>(elig   + (size_t)row * IN_DIM);
    float4*       out4 = reinterpret_cast<float4*>(out + 3 * (size_t)OUT_DIM + (size_t)row * IN_DIM);

    // ---- phase 1: binary-weight GEMV dot product ----
    // rows < PIN_ROWS: evict_last -> stay L2-resident across graph replays.
    // rest: evict_first streaming. spike_input: evict_last (32 KB, always hot).
    float acc = 0.0f;
    #pragma unroll
    for (int it = 0; it < VPT; ++it) {
        const int i = it * TPB + tid;
        float4 s  = ldg_hint(&st4[i], pol_states);
        float4 sp = ldg_hint(&sp4[i], pol_last);
        if (s.x > THRESH) acc += sp.x;
        if (s.y > THRESH) acc += sp.y;
        if (s.z > THRESH) acc += sp.z;
        if (s.w > THRESH) acc += sp.w;
    }

    // ---- block reduction ----
    #pragma unroll
    for (int off = 16; off > 0; off >>= 1)
        acc += __shfl_xor_sync(0xFFFFFFFFu, acc, off);
    if ((tid & 31) == 0) s_warp[tid >> 5] = acc;
    __syncthreads();

    if (tid < 32) {
        float total = (tid < TPB / 32) ? s_warp[tid] : 0.0f;
        #pragma unroll
        for (int off = 4; off > 0; off >>= 1)
            total += __shfl_xor_sync(0xFFFFFFFFu, total, off);

        if (tid == 0) {
            const float vth   = v_th[row];
            const float v_new = v_mem[row] * 0.8f + total + noise[row];
            const float spk   = (v_new >= vth) ? 1.0f : 0.0f;

            // outputs: [spikes | v_mem_new | v_th_new | elig_new]
            out[row]           = spk;
            out[OUT_DIM + row] = v_new * (1.0f - spk) * 0.2f;
            float vth_new = vth + (spk - 0.05f) * 0.1f;
            out[2 * OUT_DIM + row] = fminf(fmaxf(vth_new, 0.5f), 10.0f);

            s_spk = spk;
        }
    }
    __syncthreads();

    // ---- phase 2: eligibility trace update (pure stream: evict-first) ----
    const float spk = s_spk;
    #pragma unroll
    for (int it = 0; it < VPT; ++it) {
        const int i = it * TPB + tid;
        float4 e  = ldg_hint(&el4[i], pol_first);
        float4 sp = ldg_hint(&sp4[i], pol_last);   // L2 hit
        float4 r;
        r.x = fminf(fmaxf(fmaf(e.x, 0.95f, spk * sp.x), 0.0f), 5.0f);
        r.y = fminf(fmaxf(fmaf(e.y, 0.95f, spk * sp.y), 0.0f), 5.0f);
        r.z = fminf(fmaxf(fmaf(e.z, 0.95f, spk * sp.z), 0.0f), 5.0f);
        r.w = fminf(fmaxf(fmaf(e.w, 0.95f, spk * sp.w), 0.0f), 5.0f);
        stg_hint(&out4[i], r, pol_first);
    }
}

extern "C" void kernel_launch(void* const* d_in, const int* in_sizes, int n_in,
                              void* d_out, int out_size)
{
    const float* spike_input = (const float*)d_in[0];
    const float* states      = (const float*)d_in[1];
    const float* v_mem       = (const float*)d_in[2];
    const float* v_th        = (const float*)d_in[3];
    const float* elig        = (const float*)d_in[4];
    const float* noise       = (const float*)d_in[5];
    float* out = (float*)d_out;

    snn_fused_kernel<<<OUT_DIM, TPB>>>(spike_input, states, v_mem, v_th,
                                       elig, noise, out);
}

// round 5
// speedup vs baseline: 1.0865x; 1.0865x over previous
#include <cuda_runtime.h>
#include <cstdint>

#define IN_DIM  8192
#define OUT_DIM 8192
#define TPB     256
#define VPT8    (IN_DIM / 8 / TPB)   // 256-bit loads per thread per row = 4
#define THRESH  50.0f

// 256-bit streaming load (evict_first) — sm_103a LDG.E.256
__device__ __forceinline__ void ldg256_ef(const float* p, float* v) {
    asm volatile("ld.global.L2::evict_first.v8.b32 {%0,%1,%2,%3,%4,%5,%6,%7}, [%8];"
                 : "=f"(v[0]), "=f"(v[1]), "=f"(v[2]), "=f"(v[3]),
                   "=f"(v[4]), "=f"(v[5]), "=f"(v[6]), "=f"(v[7])
                 : "l"(p));
}
// 256-bit default-policy load (for the small, reused spike_input)
__device__ __forceinline__ void ldg256(const float* p, float* v) {
    asm volatile("ld.global.v8.b32 {%0,%1,%2,%3,%4,%5,%6,%7}, [%8];"
                 : "=f"(v[0]), "=f"(v[1]), "=f"(v[2]), "=f"(v[3]),
                   "=f"(v[4]), "=f"(v[5]), "=f"(v[6]), "=f"(v[7])
                 : "l"(p));
}
// 256-bit streaming store — sm_103a STG.E.256
__device__ __forceinline__ void stg256_ef(float* p, const float* v) {
    asm volatile("st.global.L2::evict_first.v8.b32 [%0], {%1,%2,%3,%4,%5,%6,%7,%8};"
                 :: "l"(p),
                    "f"(v[0]), "f"(v[1]), "f"(v[2]), "f"(v[3]),
                    "f"(v[4]), "f"(v[5]), "f"(v[6]), "f"(v[7])
                 : "memory");
}

__global__ __launch_bounds__(TPB)
void snn_fused_kernel(const float* __restrict__ spike_input,
                      const float* __restrict__ states,
                      const float* __restrict__ v_mem,
                      const float* __restrict__ v_th,
                      const float* __restrict__ elig,
                      const float* __restrict__ noise,
                      float* __restrict__ out)
{
    __shared__ float s_warp[TPB / 32];
    __shared__ float s_spk;

    const int row = blockIdx.x;
    const int tid = threadIdx.x;

    const float* st_row = states + (size_t)row * IN_DIM;
    const float* el_row = elig   + (size_t)row * IN_DIM;
    float*       out_row = out + 3 * (size_t)OUT_DIM + (size_t)row * IN_DIM;

    // ---- phase 1: binary-weight GEMV dot product (256-bit streams) ----
    float acc = 0.0f;
    #pragma unroll
    for (int it = 0; it < VPT8; ++it) {
        const int off = (it * TPB + tid) * 8;
        float s[8], sp[8];
        ldg256_ef(st_row + off, s);
        ldg256(spike_input + off, sp);
        #pragma unroll
        for (int j = 0; j < 8; ++j)
            if (s[j] > THRESH) acc += sp[j];
    }

    // ---- block reduction ----
    #pragma unroll
    for (int off = 16; off > 0; off >>= 1)
        acc += __shfl_xor_sync(0xFFFFFFFFu, acc, off);
    if ((tid & 31) == 0) s_warp[tid >> 5] = acc;
    __syncthreads();

    if (tid < 32) {
        float total = (tid < TPB / 32) ? s_warp[tid] : 0.0f;
        #pragma unroll
        for (int off = 4; off > 0; off >>= 1)
            total += __shfl_xor_sync(0xFFFFFFFFu, total, off);

        if (tid == 0) {
            const float vth   = v_th[row];
            const float v_new = v_mem[row] * 0.8f + total + noise[row];
            const float spk   = (v_new >= vth) ? 1.0f : 0.0f;

            // outputs: [spikes | v_mem_new | v_th_new | elig_new]
            out[row]           = spk;
            out[OUT_DIM + row] = v_new * (1.0f - spk) * 0.2f;
            float vth_new = vth + (spk - 0.05f) * 0.1f;
            out[2 * OUT_DIM + row] = fminf(fmaxf(vth_new, 0.5f), 10.0f);

            s_spk = spk;
        }
    }
    __syncthreads();

    // ---- phase 2: eligibility trace update (256-bit streams) ----
    const float spk = s_spk;
    #pragma unroll
    for (int it = 0; it < VPT8; ++it) {
        const int off = (it * TPB + tid) * 8;
        float e[8], sp[8], r[8];
        ldg256_ef(el_row + off, e);
        ldg256(spike_input + off, sp);   // L1 hit (same addrs as phase 1)
        #pragma unroll
        for (int j = 0; j < 8; ++j)
            r[j] = fminf(fmaxf(fmaf(e[j], 0.95f, spk * sp[j]), 0.0f), 5.0f);
        stg256_ef(out_row + off, r);
    }
}

extern "C" void kernel_launch(void* const* d_in, const int* in_sizes, int n_in,
                              void* d_out, int out_size)
{
    const float* spike_input = (const float*)d_in[0];
    const float* states      = (const float*)d_in[1];
    const float* v_mem       = (const float*)d_in[2];
    const float* v_th        = (const float*)d_in[3];
    const float* elig        = (const float*)d_in[4];
    const float* noise       = (const float*)d_in[5];
    float* out = (float*)d_out;

    snn_fused_kernel<<<OUT_DIM, TPB>>>(spike_input, states, v_mem, v_th,
                                       elig, noise, out);
}